// round 2
// baseline (speedup 1.0000x reference)
#include <cuda_runtime.h>
#include <math.h>
#include <stdint.h>

// Problem constants
#define B_    4
#define N_    8192
#define D_    1024
#define DL_   512
#define DH_   4096
#define KSEL  1024
#define NITERS 50
#define EPS_  1.0f
#define KEFF  1152.0f   // min(1024 * 9/8, 8192)

// ---------------- scratch (static device globals; no allocation) ----------------
__device__ float g_s[B_ * N_];
__device__ float g_rscale[B_ * N_];
__device__ int   g_sel[B_ * KSEL];
__device__ float g_w1g[D_ * DL_];          // light_w1 with gamma folded   (2 MB)
__device__ float g_w1hg[D_ * DH_];         // heavy_w1 with gamma folded   (16 MB)
__device__ float g_Hl[16777216];           // light hidden 32768 x 512     (64 MB)
__device__ float g_Hh[16777216];           // heavy hidden 4096 x 4096     (64 MB)

// ---------------- helpers ----------------
__device__ __forceinline__ float gelu_exact(float v) {
    return 0.5f * v * (1.0f + erff(v * 0.7071067811865475f));
}

__device__ __forceinline__ float warpMaxF(float v) {
    #pragma unroll
    for (int o = 16; o > 0; o >>= 1) v = fmaxf(v, __shfl_down_sync(0xffffffffu, v, o));
    return v;
}
__device__ __forceinline__ double warpSumD(double v) {
    #pragma unroll
    for (int o = 16; o > 0; o >>= 1) v += __shfl_down_sync(0xffffffffu, v, o);
    return v;
}
__device__ __forceinline__ int warpSumI(int v) {
    #pragma unroll
    for (int o = 16; o > 0; o >>= 1) v += __shfl_down_sync(0xffffffffu, v, o);
    return v;
}

// Block-wide reduce-max over 1024 threads (32 warps). smf: >=32 floats.
__device__ float blockMaxF(float v, float* smf) {
    int lane = threadIdx.x & 31, wid = threadIdx.x >> 5;
    v = warpMaxF(v);
    __syncthreads();                 // protect smem reuse across calls
    if (lane == 0) smf[wid] = v;
    __syncthreads();
    if (wid == 0) {
        float t = smf[lane];
        t = warpMaxF(t);
        if (lane == 0) smf[0] = t;
    }
    __syncthreads();
    return smf[0];
}

// Block-wide sum (double) over 1024 threads. smd: >=32 doubles.
__device__ double blockSumD(double v, double* smd) {
    int lane = threadIdx.x & 31, wid = threadIdx.x >> 5;
    v = warpSumD(v);
    __syncthreads();
    if (lane == 0) smd[wid] = v;
    __syncthreads();
    if (wid == 0) {
        double t = smd[lane];
        t = warpSumD(t);
        if (lane == 0) smd[0] = t;
    }
    __syncthreads();
    return smd[0];
}

// Block-wide int sum over 1024 threads. smi: >=33 ints.
__device__ int blockSumI(int v, int* smi) {
    int lane = threadIdx.x & 31, wid = threadIdx.x >> 5;
    v = warpSumI(v);
    __syncthreads();
    if (lane == 0) smi[wid] = v;
    __syncthreads();
    if (wid == 0) {
        int t = smi[lane];
        t = warpSumI(t);
        if (lane == 0) smi[32] = t;
    }
    __syncthreads();
    return smi[32];
}

// Block-wide exclusive scan over per-thread values, 1024 threads. smi: >=33 ints.
__device__ int blockScanExclI(int v, int* smi) {
    int lane = threadIdx.x & 31, wid = threadIdx.x >> 5;
    int incl = v;
    #pragma unroll
    for (int o = 1; o < 32; o <<= 1) {
        int t = __shfl_up_sync(0xffffffffu, incl, o);
        if (lane >= o) incl += t;
    }
    __syncthreads();
    if (lane == 31) smi[wid] = incl;
    __syncthreads();
    if (wid == 0) {
        int t = smi[lane];
        int inc2 = t;
        #pragma unroll
        for (int o = 1; o < 32; o <<= 1) {
            int u = __shfl_up_sync(0xffffffffu, inc2, o);
            if (lane >= o) inc2 += u;
        }
        smi[lane] = inc2 - t;   // exclusive warp offsets
    }
    __syncthreads();
    return incl - v + smi[wid];
}

__device__ __forceinline__ unsigned f2ord(float f) {
    unsigned u = __float_as_uint(f);
    return (u & 0x80000000u) ? ~u : (u | 0x80000000u);
}

// ---------------- kernel 0: fold gamma into W1 ----------------
__global__ void fold_gamma_kernel(const float* __restrict__ w, const float* __restrict__ g,
                                  float* __restrict__ o, int N, int total) {
    int i = blockIdx.x * blockDim.x + threadIdx.x;
    if (i < total) o[i] = w[i] * g[i / N];
}

// ---------------- kernel 1: routing score + rms scale, one warp / token ----------------
__global__ void score_norm_kernel(const float* __restrict__ x, const float* __restrict__ rt,
                                  float* __restrict__ s, float* __restrict__ rs) {
    int warp = (blockIdx.x * blockDim.x + threadIdx.x) >> 5;
    int lane = threadIdx.x & 31;
    if (warp >= B_ * N_) return;
    const float4* xr = (const float4*)(x + (size_t)warp * D_);
    const float4* rr = (const float4*)rt;
    float dot = 0.f, ss = 0.f;
    #pragma unroll 4
    for (int i = lane; i < D_ / 4; i += 32) {
        float4 v = xr[i], r = rr[i];
        dot += v.x * r.x + v.y * r.y + v.z * r.z + v.w * r.w;
        ss  += v.x * v.x + v.y * v.y + v.z * v.z + v.w * v.w;
    }
    #pragma unroll
    for (int o = 16; o > 0; o >>= 1) {
        dot += __shfl_down_sync(0xffffffffu, dot, o);
        ss  += __shfl_down_sync(0xffffffffu, ss, o);
    }
    if (lane == 0) {
        s[warp]  = dot;
        rs[warp] = 32.0f / fmaxf(sqrtf(ss), 1e-12f);   // sqrt(1024)=32
    }
}

// ---------------- kernel 2: coordinate descent + exact tie-aware top-k ----------------
// One 1024-thread block per batch row; each thread owns 8 consecutive tokens.
__global__ void __launch_bounds__(1024) router_kernel(const float* __restrict__ s_glob,
                                                      int* __restrict__ sel) {
    __shared__ float  smf[32];
    __shared__ double smd[32];
    __shared__ int    smi[33];
    __shared__ float  a_sh;

    const int tid = threadIdx.x;
    const int b   = blockIdx.x;
    const float* s = s_glob + (size_t)b * N_;

    float sv[8], bv[8];
    #pragma unroll
    for (int i = 0; i < 8; i++) { sv[i] = s[tid * 8 + i]; bv[i] = -sv[i]; }

    const float logk = logf(KEFF);
    const float inv_eps = 1.0f / EPS_;
    float a = 0.f;

    for (int it = 0; it < NITERS; ++it) {
        float m = -INFINITY;
        #pragma unroll
        for (int i = 0; i < 8; i++) m = fmaxf(m, (sv[i] + bv[i]) * inv_eps);
        m = blockMaxF(m, smf);

        double sum = 0.0;
        #pragma unroll
        for (int i = 0; i < 8; i++) sum += (double)expf((sv[i] + bv[i]) * inv_eps - m);
        sum = blockSumD(sum, smd);

        if (tid == 0) a_sh = EPS_ * (logk - (m + (float)log(sum)));
        __syncthreads();
        a = a_sh;
        #pragma unroll
        for (int i = 0; i < 8; i++) bv[i] = -fmaxf(sv[i] + a, 0.0f);
    }

    // Selection key: score = exp(min(s + a, 0)); monotone in key = min(s+a, 0).
    // Saturated tokens (key == 0) all score exactly 1.0 -> top_k ties -> lowest index first.
    unsigned ord[8];
    #pragma unroll
    for (int i = 0; i < 8; i++) {
        float key = fminf(sv[i] + a, 0.0f);
        ord[i] = f2ord(key);
    }

    // Radix-select the KSEL-th largest key (exact, with tie accounting).
    unsigned p = 0; int Cgt = 0;
    for (int bit = 31; bit >= 0; --bit) {
        unsigned cand = (p >> bit) | 1u;
        int c = 0;
        #pragma unroll
        for (int i = 0; i < 8; i++) c += ((ord[i] >> bit) == cand);
        c = blockSumI(c, smi);
        if (Cgt + c >= KSEL) p |= (1u << bit);
        else                 Cgt += c;
    }
    const int need_eq = KSEL - Cgt;   // how many ties at p to take (lowest index first)

    // rank among equal-to-threshold elements (index order)
    int eqc = 0; bool eqf[8];
    #pragma unroll
    for (int i = 0; i < 8; i++) { eqf[i] = (ord[i] == p); eqc += eqf[i] ? 1 : 0; }
    int eq_excl = blockScanExclI(eqc, smi);

    bool self_[8]; int selc = 0; int eqrun = 0;
    #pragma unroll
    for (int i = 0; i < 8; i++) {
        bool sgt = ord[i] > p;
        bool se  = eqf[i] && (eq_excl + eqrun < need_eq);
        eqrun += eqf[i] ? 1 : 0;
        self_[i] = sgt || se;
        selc += self_[i] ? 1 : 0;
    }
    int slot = blockScanExclI(selc, smi);
    #pragma unroll
    for (int i = 0; i < 8; i++) {
        if (self_[i]) { sel[b * KSEL + slot] = b * N_ + tid * 8 + i; slot++; }
    }
}

// ---------------- kernel 3: tiled SGEMM with fused epilogues ----------------
// C[M,N] = op( A[M,K] @ B[K,N] ).  BM=BN=128, BK=8, 256 threads, 8x8 microtile.
// mode 0: store gelu(acc * rscale[arow] + bias[col])        (compact C rows)
// mode 1: store acc + bias[col]                             (direct rows)
// mode 2: C[cmap[row]] += acc + bias[col]                   (scatter-accumulate)
__global__ void __launch_bounds__(256) sgemm_kernel(
    const float* __restrict__ A, const float* __restrict__ B,
    float* __restrict__ C, const float* __restrict__ bias,
    const float* __restrict__ rscale,
    const int* __restrict__ amap, const int* __restrict__ cmap,
    int M, int N, int K, int mode)
{
    __shared__ float As[8][128];
    __shared__ float Bs[8][128];

    const int tid = threadIdx.x;
    const int bx = blockIdx.x, by = blockIdx.y;

    // A tile loader: 128 rows x 8 cols per step; one float4 per thread.
    const int aRow = tid >> 1;
    const int aCol = (tid & 1) << 2;
    const int aGrow = by * 128 + aRow;
    const int aIdx  = amap ? amap[aGrow] : aGrow;
    const float* Ap = A + (size_t)aIdx * K + aCol;

    // B tile loader: 8 rows x 128 cols; one float4 per thread.
    const int bRow = tid >> 5;
    const int bCol = (tid & 31) << 2;
    const float* Bp = B + (size_t)bRow * N + (size_t)bx * 128 + bCol;

    float acc[8][8];
    #pragma unroll
    for (int i = 0; i < 8; i++)
        #pragma unroll
        for (int j = 0; j < 8; j++) acc[i][j] = 0.f;

    const int tx = tid & 15, ty = tid >> 4;

    for (int k0 = 0; k0 < K; k0 += 8) {
        float4 av = *(const float4*)(Ap + k0);
        float4 bv = *(const float4*)(Bp + (size_t)k0 * N);
        As[aCol + 0][aRow] = av.x;
        As[aCol + 1][aRow] = av.y;
        As[aCol + 2][aRow] = av.z;
        As[aCol + 3][aRow] = av.w;
        *(float4*)(&Bs[bRow][bCol]) = bv;
        __syncthreads();
        #pragma unroll
        for (int kk = 0; kk < 8; kk++) {
            float4 a0 = *(const float4*)(&As[kk][ty * 8]);
            float4 a1 = *(const float4*)(&As[kk][ty * 8 + 4]);
            float4 b0 = *(const float4*)(&Bs[kk][tx * 8]);
            float4 b1 = *(const float4*)(&Bs[kk][tx * 8 + 4]);
            float ar[8] = {a0.x, a0.y, a0.z, a0.w, a1.x, a1.y, a1.z, a1.w};
            float br[8] = {b0.x, b0.y, b0.z, b0.w, b1.x, b1.y, b1.z, b1.w};
            #pragma unroll
            for (int i = 0; i < 8; i++)
                #pragma unroll
                for (int j = 0; j < 8; j++)
                    acc[i][j] = fmaf(ar[i], br[j], acc[i][j]);
        }
        __syncthreads();
    }

    const int rowBase = by * 128 + ty * 8;
    const int colBase = bx * 128 + tx * 8;

    if (mode == 0) {
        #pragma unroll
        for (int i = 0; i < 8; i++) {
            int row  = rowBase + i;
            int xrow = amap ? amap[row] : row;
            float r  = rscale[xrow];
            float* cp = C + (size_t)row * N + colBase;
            #pragma unroll
            for (int j = 0; j < 8; j++) {
                float v = fmaf(acc[i][j], r, bias[colBase + j]);
                cp[j] = gelu_exact(v);
            }
        }
    } else if (mode == 1) {
        #pragma unroll
        for (int i = 0; i < 8; i++) {
            float* cp = C + (size_t)(rowBase + i) * N + colBase;
            #pragma unroll
            for (int j = 0; j < 8; j++) cp[j] = acc[i][j] + bias[colBase + j];
        }
    } else {
        #pragma unroll
        for (int i = 0; i < 8; i++) {
            int orow = cmap[rowBase + i];
            float* cp = C + (size_t)orow * N + colBase;
            #pragma unroll
            for (int j = 0; j < 8; j++) cp[j] += acc[i][j] + bias[colBase + j];
        }
    }
}

// ---------------- launch ----------------
extern "C" void kernel_launch(void* const* d_in, const int* in_sizes, int n_in,
                              void* d_out, int out_size) {
    const float* x      = (const float*)d_in[0];
    const float* rt     = (const float*)d_in[1];
    const float* lgam   = (const float*)d_in[2];
    const float* lw1    = (const float*)d_in[3];
    const float* lb1    = (const float*)d_in[4];
    const float* lw2    = (const float*)d_in[5];
    const float* lb2    = (const float*)d_in[6];
    const float* hgam   = (const float*)d_in[7];
    const float* hw1    = (const float*)d_in[8];
    const float* hb1    = (const float*)d_in[9];
    const float* hw2    = (const float*)d_in[10];
    const float* hb2    = (const float*)d_in[11];
    float* out = (float*)d_out;

    void *s_p, *rs_p, *sel_p, *w1g_p, *w1hg_p, *Hl_p, *Hh_p;
    cudaGetSymbolAddress(&s_p,    g_s);
    cudaGetSymbolAddress(&rs_p,   g_rscale);
    cudaGetSymbolAddress(&sel_p,  g_sel);
    cudaGetSymbolAddress(&w1g_p,  g_w1g);
    cudaGetSymbolAddress(&w1hg_p, g_w1hg);
    cudaGetSymbolAddress(&Hl_p,   g_Hl);
    cudaGetSymbolAddress(&Hh_p,   g_Hh);

    // fold gamma into W1 (light and heavy)
    {
        int totL = D_ * DL_;
        fold_gamma_kernel<<<(totL + 255) / 256, 256>>>(lw1, lgam, (float*)w1g_p, DL_, totL);
        int totH = D_ * DH_;
        fold_gamma_kernel<<<(totH + 255) / 256, 256>>>(hw1, hgam, (float*)w1hg_p, DH_, totH);
    }

    // routing scores + rms scales (one warp per token)
    score_norm_kernel<<<(B_ * N_) / 8, 256>>>(x, rt, (float*)s_p, (float*)rs_p);

    // coordinate descent + top-k selection (one block per batch row)
    router_kernel<<<B_, 1024>>>((const float*)s_p, (int*)sel_p);

    // light branch: H = gelu(rms(x) @ (gamma*W1) + b1);  out = H @ W2 + b2
    sgemm_kernel<<<dim3(DL_ / 128, (B_ * N_) / 128), 256>>>(
        x, (const float*)w1g_p, (float*)Hl_p, lb1, (const float*)rs_p,
        nullptr, nullptr, B_ * N_, DL_, D_, 0);
    sgemm_kernel<<<dim3(D_ / 128, (B_ * N_) / 128), 256>>>(
        (const float*)Hl_p, lw2, out, lb2, nullptr,
        nullptr, nullptr, B_ * N_, D_, DL_, 1);

    // heavy branch on gathered tokens; scatter-accumulate into out
    sgemm_kernel<<<dim3(DH_ / 128, (B_ * KSEL) / 128), 256>>>(
        x, (const float*)w1hg_p, (float*)Hh_p, hb1, (const float*)rs_p,
        (const int*)sel_p, nullptr, B_ * KSEL, DH_, D_, 0);
    sgemm_kernel<<<dim3(D_ / 128, (B_ * KSEL) / 128), 256>>>(
        (const float*)Hh_p, hw2, out, hb2, nullptr,
        nullptr, (const int*)sel_p, B_ * KSEL, D_, DH_, 2);
}